// round 2
// baseline (speedup 1.0000x reference)
#include <cuda_runtime.h>

// Problem constants
#define BB 4
#define NN 20000
#define EE 320000
#define ED 64
#define HH 128
#define INDIM 21
#define NLAYER 3
#define BN_EPS 1e-5f

// ---------------- scratch (device globals; no allocation allowed) ----------
__device__ float g_H0[BB*NN*ED];     // ping node embeddings
__device__ float g_H1[BB*NN*ED];     // pong node embeddings
__device__ float g_AGG[BB*NN*ED];    // segment-sum of h[src]
__device__ float g_S[BB*NN];         // segment-sum of edge_attr
__device__ float g_DEG[BB*NN];       // in-degree (float)
__device__ float g_Z[BB*NN*HH];      // pre-BN activations
__device__ float g_STATS[BB*2*HH];   // per-graph channel sum / sumsq
__device__ float g_UV[2*HH];         // u, v  (edgeW@W1[64:], edgeb@W1[64:])
__device__ float g_AB[BB*2*HH];      // BN fused scale a, shift bb
__device__ int   g_is64;             // edge_index dtype flag

// ---------------- dtype detection for edge_index ---------------------------
// If data is int64 (little-endian), every odd int32 word is a high word == 0
// (indices < 20000). If int32, odd words are random indices, ~never all zero.
__global__ void detect_kernel(const int* __restrict__ ei) {
    int any = 0;
    for (int i = threadIdx.x; i < 4096; i += blockDim.x) {
        int p = 2 * (i * 312) + 1;   // max 2,555,281 < 2,560,000 (safe either way)
        if (ei[p] != 0) any = 1;
    }
    any = __syncthreads_or(any);
    if (threadIdx.x == 0) g_is64 = any ? 0 : 1;
}

// ---------------- layer-0 input embedding: H0 = x @ inW + inb --------------
__global__ void input_embed_kernel(const float* __restrict__ x,
                                   const float* __restrict__ inW,
                                   const float* __restrict__ inb) {
    __shared__ float sx[INDIM];
    int row = blockIdx.x;            // 0 .. B*N-1
    int c = threadIdx.x;             // 0 .. 63
    if (c < INDIM) sx[c] = x[row * INDIM + c];
    __syncthreads();
    float acc = inb[c];
#pragma unroll
    for (int k = 0; k < INDIM; k++) acc = fmaf(sx[k], inW[k * ED + c], acc);
    g_H0[row * ED + c] = acc;
}

// ---------------- zero per-layer scratch -----------------------------------
__global__ void zero_kernel() {
    int stride = gridDim.x * blockDim.x;
    int tid = blockIdx.x * blockDim.x + threadIdx.x;
    float4 z4 = make_float4(0.f, 0.f, 0.f, 0.f);
    for (int i = tid; i < BB * NN * ED / 4; i += stride) ((float4*)g_AGG)[i] = z4;
    for (int i = tid; i < BB * NN; i += stride) { g_S[i] = 0.f; g_DEG[i] = 0.f; }
    if (tid < BB * 2 * HH) g_STATS[tid] = 0.f;
}

// ---------------- u/v precompute: fold edge encoder through W1 bottom half -
__global__ void uv_kernel(const float* __restrict__ edgeW,
                          const float* __restrict__ edgeb,
                          const float* __restrict__ W1, int l) {
    int c = threadIdx.x;             // 0..127
    const float* Wl = W1 + l * HH * HH + ED * HH;   // rows 64..127
    float u = 0.f, v = 0.f;
    for (int k = 0; k < ED; k++) {
        float w = Wl[k * HH + c];
        u = fmaf(edgeW[l * ED + k], w, u);
        v = fmaf(edgeb[l * ED + k], w, v);
    }
    g_UV[c] = u;
    g_UV[HH + c] = v;
}

// ---------------- scatter: AGG[dst] += Hin[src]; S[dst]+=attr; DEG[dst]++ --
__global__ void scatter_kernel(const int* __restrict__ ei,
                               const float* __restrict__ eattr, int insel) {
    const float* Hin = insel ? g_H1 : g_H0;
    int gid = blockIdx.x * blockDim.x + threadIdx.x;   // B*E*16 = 20.48M
    int eidx = gid >> 4;
    int lane = gid & 15;
    int b = eidx / EE;
    int e = eidx - b * EE;
    int base = b * 2 * EE;
    int src, dst;
    if (g_is64) { src = ei[2 * (base + e)]; dst = ei[2 * (base + EE + e)]; }
    else        { src = ei[base + e];       dst = ei[base + EE + e];       }
    float4 v = ((const float4*)(Hin + (b * NN + src) * ED))[lane];
    float* ap = g_AGG + (b * NN + dst) * ED + lane * 4;
    asm volatile("red.global.add.v4.f32 [%0], {%1,%2,%3,%4};"
                 :: "l"(ap), "f"(v.x), "f"(v.y), "f"(v.z), "f"(v.w) : "memory");
    if (lane == 0) {
        atomicAdd(&g_S[b * NN + dst], eattr[eidx]);
        atomicAdd(&g_DEG[b * NN + dst], 1.0f);
    }
}

// ---------------- GEMM1 + BN stats -----------------------------------------
// Z = AGG @ W1[:64,:] + s*u + deg*v + b1, plus per-channel sum/sumsq atomics.
// Tile: 64 rows x 128 cols per 256-thread block; thread = 4 rows x 8 cols.
__global__ void __launch_bounds__(256) gemm1_kernel(const float* __restrict__ W1,
                                                    const float* __restrict__ b1,
                                                    int l) {
    extern __shared__ float sm[];
    float* sW   = sm;                 // 64*128
    float* sA   = sW + 64 * HH;       // 64*65 (pad for conflict-free reads)
    float* sS   = sA + 64 * 65;       // 64
    float* sD   = sS + 64;            // 64
    float* sU   = sD + 64;            // 128
    float* sV   = sU + HH;            // 128
    float* sB   = sV + HH;            // 128
    float* sSum = sB + HH;            // 128
    float* sSq  = sSum + HH;          // 128

    int tid = threadIdx.x;
    int b = blockIdx.y;
    int r0 = blockIdx.x * 64;

    const float4* Wg = (const float4*)(W1 + l * HH * HH);   // rows 0..63
    float4* sWv = (float4*)sW;
#pragma unroll
    for (int i = 0; i < 8; i++) sWv[tid + i * 256] = Wg[tid + i * 256];

    if (tid < HH) {
        sU[tid] = g_UV[tid];
        sV[tid] = g_UV[HH + tid];
        sB[tid] = b1[l * HH + tid];
        sSum[tid] = 0.f; sSq[tid] = 0.f;
    }
    if (tid < 64) {
        int r = r0 + tid;
        bool valid = r < NN;
        sS[tid] = valid ? g_S[b * NN + r] : 0.f;
        sD[tid] = valid ? g_DEG[b * NN + r] : 0.f;
    }
    {
        const float* Ag = g_AGG + b * NN * ED;
#pragma unroll
        for (int i = 0; i < 16; i++) {
            int idx = tid + i * 256;
            int r = idx >> 6, k = idx & 63;
            float v = 0.f;
            if (r0 + r < NN) v = Ag[(r0 + r) * ED + k];
            sA[r * 65 + k] = v;
        }
    }
    __syncthreads();

    int tx = tid & 15, ty = tid >> 4;
    int c0 = tx * 4;                 // cols: c0..c0+3 and 64+c0..64+c0+3
    float acc[4][8];
#pragma unroll
    for (int j = 0; j < 4; j++)
#pragma unroll
        for (int c = 0; c < 8; c++) acc[j][c] = 0.f;

#pragma unroll 8
    for (int k = 0; k < ED; k++) {
        float a[4];
#pragma unroll
        for (int j = 0; j < 4; j++) a[j] = sA[(4 * ty + j) * 65 + k];
        float4 w0 = *(const float4*)&sW[k * HH + c0];
        float4 w1 = *(const float4*)&sW[k * HH + 64 + c0];
#pragma unroll
        for (int j = 0; j < 4; j++) {
            acc[j][0] = fmaf(a[j], w0.x, acc[j][0]);
            acc[j][1] = fmaf(a[j], w0.y, acc[j][1]);
            acc[j][2] = fmaf(a[j], w0.z, acc[j][2]);
            acc[j][3] = fmaf(a[j], w0.w, acc[j][3]);
            acc[j][4] = fmaf(a[j], w1.x, acc[j][4]);
            acc[j][5] = fmaf(a[j], w1.y, acc[j][5]);
            acc[j][6] = fmaf(a[j], w1.z, acc[j][6]);
            acc[j][7] = fmaf(a[j], w1.w, acc[j][7]);
        }
    }

    float colsum[8], colsq[8];
#pragma unroll
    for (int c = 0; c < 8; c++) { colsum[c] = 0.f; colsq[c] = 0.f; }

#pragma unroll
    for (int j = 0; j < 4; j++) {
        int r = 4 * ty + j;
        int gr = r0 + r;
        if (gr < NN) {
            float s = sS[r], d = sD[r];
            float z[8];
#pragma unroll
            for (int c = 0; c < 8; c++) {
                int col = (c < 4) ? (c0 + c) : (64 + c0 + c - 4);
                float zz = acc[j][c] + s * sU[col] + d * sV[col] + sB[col];
                z[c] = zz;
                colsum[c] += zz;
                colsq[c] += zz * zz;
            }
            *(float4*)(g_Z + (b * NN + gr) * HH + c0)      = make_float4(z[0], z[1], z[2], z[3]);
            *(float4*)(g_Z + (b * NN + gr) * HH + 64 + c0) = make_float4(z[4], z[5], z[6], z[7]);
        }
    }
#pragma unroll
    for (int c = 0; c < 8; c++) {
        int col = (c < 4) ? (c0 + c) : (64 + c0 + c - 4);
        atomicAdd(&sSum[col], colsum[c]);
        atomicAdd(&sSq[col], colsq[c]);
    }
    __syncthreads();
    if (tid < HH) {
        atomicAdd(&g_STATS[b * 2 * HH + tid], sSum[tid]);
        atomicAdd(&g_STATS[b * 2 * HH + HH + tid], sSq[tid]);
    }
}

// ---------------- BN finalize: fused scale/shift per (graph, channel) ------
__global__ void bnfin_kernel(const float* __restrict__ gamma,
                             const float* __restrict__ beta, int l) {
    int i = threadIdx.x;             // 512 = B*128
    int b = i >> 7, c = i & 127;
    float sum = g_STATS[b * 2 * HH + c];
    float sq  = g_STATS[b * 2 * HH + HH + c];
    float m = sum * (1.0f / NN);
    float var = sq * (1.0f / NN) - m * m;
    float rs = rsqrtf(var + BN_EPS);
    float a = gamma[l * HH + c] * rs;
    g_AB[b * 2 * HH + c] = a;
    g_AB[b * 2 * HH + HH + c] = beta[l * HH + c] - m * a;
}

// ---------------- BN+ReLU+GEMM2 (+optional outer ReLU) ---------------------
// out = relu?(relu(z*a+bb) @ W2 + b2). Tile 64x64 per 256 threads.
__global__ void __launch_bounds__(256) gemm2_kernel(const float* __restrict__ W2,
                                                    const float* __restrict__ b2,
                                                    int l, int outsel,
                                                    float* __restrict__ dout,
                                                    int relu_out) {
    extern __shared__ float sm[];
    float* sW  = sm;                  // 128*64
    float* sT  = sW + HH * ED;        // 64*132 (pad 132, 16B-aligned rows)
    float* sa  = sT + 64 * 132;       // 128
    float* sbb = sa + HH;             // 128
    float* sb2 = sbb + HH;            // 64

    int tid = threadIdx.x;
    int b = blockIdx.y;
    int r0 = blockIdx.x * 64;

    const float4* Wg = (const float4*)(W2 + l * HH * ED);
    float4* sWv = (float4*)sW;
#pragma unroll
    for (int i = 0; i < 8; i++) sWv[tid + i * 256] = Wg[tid + i * 256];
    if (tid < HH) { sa[tid] = g_AB[b * 2 * HH + tid]; sbb[tid] = g_AB[b * 2 * HH + HH + tid]; }
    if (tid < ED) sb2[tid] = b2[l * ED + tid];
    __syncthreads();

    // load z tile, apply BN + ReLU on the fly
#pragma unroll
    for (int i = 0; i < 8; i++) {
        int idx4 = tid + i * 256;     // 2048 float4 = 64 rows * 32
        int r = idx4 >> 5, k4 = idx4 & 31;
        float4 v = make_float4(0.f, 0.f, 0.f, 0.f);
        if (r0 + r < NN) v = *(const float4*)(g_Z + (b * NN + r0 + r) * HH + k4 * 4);
        int k = k4 * 4;
        float t0 = fmaxf(fmaf(v.x, sa[k],     sbb[k]),     0.f);
        float t1 = fmaxf(fmaf(v.y, sa[k + 1], sbb[k + 1]), 0.f);
        float t2 = fmaxf(fmaf(v.z, sa[k + 2], sbb[k + 2]), 0.f);
        float t3 = fmaxf(fmaf(v.w, sa[k + 3], sbb[k + 3]), 0.f);
        *(float4*)&sT[r * 132 + k] = make_float4(t0, t1, t2, t3);
    }
    __syncthreads();

    int tx = tid & 15, ty = tid >> 4;
    int c0 = tx * 4;
    float acc[4][4];
#pragma unroll
    for (int j = 0; j < 4; j++)
#pragma unroll
        for (int c = 0; c < 4; c++) acc[j][c] = 0.f;

#pragma unroll 8
    for (int k = 0; k < HH; k++) {
        float4 w = *(const float4*)&sW[k * ED + c0];
#pragma unroll
        for (int j = 0; j < 4; j++) {
            float a = sT[(4 * ty + j) * 132 + k];
            acc[j][0] = fmaf(a, w.x, acc[j][0]);
            acc[j][1] = fmaf(a, w.y, acc[j][1]);
            acc[j][2] = fmaf(a, w.z, acc[j][2]);
            acc[j][3] = fmaf(a, w.w, acc[j][3]);
        }
    }

    float* outp = (outsel == 2) ? dout : (outsel ? g_H0 : g_H1);
#pragma unroll
    for (int j = 0; j < 4; j++) {
        int gr = r0 + 4 * ty + j;
        if (gr < NN) {
            float o0 = acc[j][0] + sb2[c0];
            float o1 = acc[j][1] + sb2[c0 + 1];
            float o2 = acc[j][2] + sb2[c0 + 2];
            float o3 = acc[j][3] + sb2[c0 + 3];
            if (relu_out) {
                o0 = fmaxf(o0, 0.f); o1 = fmaxf(o1, 0.f);
                o2 = fmaxf(o2, 0.f); o3 = fmaxf(o3, 0.f);
            }
            *(float4*)(outp + (b * NN + gr) * ED + c0) = make_float4(o0, o1, o2, o3);
        }
    }
}

// ---------------- launch ----------------------------------------------------
extern "C" void kernel_launch(void* const* d_in, const int* in_sizes, int n_in,
                              void* d_out, int out_size) {
    const float* x      = (const float*)d_in[0];
    const int*   ei     = (const int*)  d_in[1];
    const float* eattr  = (const float*)d_in[2];
    const float* inW    = (const float*)d_in[3];
    const float* inb    = (const float*)d_in[4];
    const float* edgeW  = (const float*)d_in[5];
    const float* edgeb  = (const float*)d_in[6];
    const float* W1     = (const float*)d_in[7];
    const float* b1     = (const float*)d_in[8];
    const float* gamma  = (const float*)d_in[9];
    const float* beta   = (const float*)d_in[10];
    const float* W2     = (const float*)d_in[11];
    const float* b2     = (const float*)d_in[12];
    float* out = (float*)d_out;

    const int G1_SMEM = (64 * HH + 64 * 65 + 64 + 64 + 5 * HH) * 4;       // 52480
    const int G2_SMEM = (HH * ED + 64 * 132 + 2 * HH + ED) * 4;           // 67840
    cudaFuncSetAttribute(gemm1_kernel, cudaFuncAttributeMaxDynamicSharedMemorySize, G1_SMEM);
    cudaFuncSetAttribute(gemm2_kernel, cudaFuncAttributeMaxDynamicSharedMemorySize, G2_SMEM);

    detect_kernel<<<1, 256>>>(ei);
    input_embed_kernel<<<BB * NN, 64>>>(x, inW, inb);

    dim3 ggrid((NN + 63) / 64, BB);
    for (int l = 0; l < NLAYER; l++) {
        int insel  = (l == 1) ? 1 : 0;                  // l0: H0, l1: H1, l2: H0
        int outsel = (l == 2) ? 2 : ((l == 0) ? 0 : 1); // l0->H1, l1->H0, l2->d_out
        zero_kernel<<<2048, 256>>>();
        uv_kernel<<<1, HH>>>(edgeW, edgeb, W1, l);
        scatter_kernel<<<(BB * EE * 16) / 256, 256>>>(ei, eattr, insel);
        gemm1_kernel<<<ggrid, 256, G1_SMEM>>>(W1, b1, l);
        bnfin_kernel<<<1, BB * HH>>>(gamma, beta, l);
        gemm2_kernel<<<ggrid, 256, G2_SMEM>>>(W2, b2, l, outsel, out, (l < NLAYER - 1) ? 1 : 0);
    }
}

// round 7
// speedup vs baseline: 1.2641x; 1.2641x over previous
#include <cuda_runtime.h>

// Problem constants
#define BB 4
#define NN 20000
#define EE 320000
#define ED 64
#define HH 128
#define INDIM 21
#define NLAYER 3
#define BN_EPS 1e-5f

// ---------------- scratch (device globals; no allocation allowed) ----------
__device__ float g_H0[BB*NN*ED];     // ping node embeddings
__device__ float g_H1[BB*NN*ED];     // pong node embeddings
__device__ float g_Z[BB*NN*HH];      // pre-BN activations
__device__ float g_S[BB*NN];         // segment-sum of edge_attr (layer-invariant)
__device__ float g_STATS[BB*2*HH];   // per-graph channel sum / sumsq
__device__ float g_UV[2*HH];         // u, v  (edgeW@W1[64:], edgeb@W1[64:])
__device__ float g_AB[BB*2*HH];      // BN fused scale a, shift bb
__device__ int   g_CNT[BB*NN];       // per-node in-degree counts
__device__ int   g_OFF[BB*(NN+1)];   // CSR offsets (per graph, within [0,EE))
__device__ int   g_CUR[BB*NN];       // fill cursors
__device__ int   g_SRC[BB*EE];       // CSR: src node per edge slot
__device__ int   g_is64;             // edge_index dtype flag

// ---------------- dtype detection for edge_index ---------------------------
__global__ void detect_kernel(const int* __restrict__ ei) {
    int any = 0;
    for (int i = threadIdx.x; i < 4096; i += blockDim.x) {
        int p = 2 * (i * 312) + 1;
        if (ei[p] != 0) any = 1;
    }
    any = __syncthreads_or(any);
    if (threadIdx.x == 0) g_is64 = any ? 0 : 1;
}

// ---------------- zero launch-invariant scratch -----------------------------
__global__ void zero_once_kernel() {
    int tid = blockIdx.x * blockDim.x + threadIdx.x;
    if (tid < BB * NN) { g_CNT[tid] = 0; g_S[tid] = 0.f; }
}

// ---------------- CSR build: count ------------------------------------------
__global__ void count_kernel(const int* __restrict__ ei,
                             const float* __restrict__ eattr) {
    int gid = blockIdx.x * blockDim.x + threadIdx.x;
    if (gid >= BB * EE) return;
    int b = gid / EE, e = gid - b * EE;
    int base = b * 2 * EE;
    int dst = g_is64 ? ei[2 * (base + EE + e)] : ei[base + EE + e];
    atomicAdd(&g_CNT[b * NN + dst], 1);
    atomicAdd(&g_S[b * NN + dst], eattr[gid]);
}

// ---------------- CSR build: per-graph exclusive scan -----------------------
#define SCAN_CH 20   // 1024*20 = 20480 >= NN
__global__ void __launch_bounds__(1024) scan_kernel() {
    int g = blockIdx.x;
    int tid = threadIdx.x;
    __shared__ int sdata[1024];
    int loc[SCAN_CH];
    int base = tid * SCAN_CH;
    int sum = 0;
#pragma unroll
    for (int i = 0; i < SCAN_CH; i++) {
        int idx = base + i;
        int v = (idx < NN) ? g_CNT[g * NN + idx] : 0;
        loc[i] = sum;            // exclusive within thread
        sum += v;
    }
    // block exclusive scan of per-thread sums (Hillis-Steele)
    sdata[tid] = sum;
    __syncthreads();
    for (int off = 1; off < 1024; off <<= 1) {
        int t = (tid >= off) ? sdata[tid - off] : 0;
        __syncthreads();
        sdata[tid] += t;
        __syncthreads();
    }
    int excl_base = sdata[tid] - sum;   // exclusive prefix for this thread
#pragma unroll
    for (int i = 0; i < SCAN_CH; i++) {
        int idx = base + i;
        if (idx < NN) {
            int o = excl_base + loc[i];
            g_OFF[g * (NN + 1) + idx] = o;
            g_CUR[g * NN + idx] = o;
        }
    }
    if (tid == 1023) g_OFF[g * (NN + 1) + NN] = sdata[1023];
}

// ---------------- CSR build: fill -------------------------------------------
__global__ void fill_kernel(const int* __restrict__ ei) {
    int gid = blockIdx.x * blockDim.x + threadIdx.x;
    if (gid >= BB * EE) return;
    int b = gid / EE, e = gid - b * EE;
    int base = b * 2 * EE;
    int src, dst;
    if (g_is64) { src = ei[2 * (base + e)]; dst = ei[2 * (base + EE + e)]; }
    else        { src = ei[base + e];       dst = ei[base + EE + e];       }
    int pos = atomicAdd(&g_CUR[b * NN + dst], 1);
    g_SRC[b * EE + pos] = src;
}

// ---------------- layer-0 input embedding: H0 = x @ inW + inb --------------
__global__ void input_embed_kernel(const float* __restrict__ x,
                                   const float* __restrict__ inW,
                                   const float* __restrict__ inb) {
    __shared__ float sx[INDIM];
    int row = blockIdx.x;
    int c = threadIdx.x;
    if (c < INDIM) sx[c] = x[row * INDIM + c];
    __syncthreads();
    float acc = inb[c];
#pragma unroll
    for (int k = 0; k < INDIM; k++) acc = fmaf(sx[k], inW[k * ED + c], acc);
    g_H0[row * ED + c] = acc;
}

// ---------------- u/v precompute + STATS zero --------------------------------
__global__ void uv_kernel(const float* __restrict__ edgeW,
                          const float* __restrict__ edgeb,
                          const float* __restrict__ W1, int l) {
    int c = threadIdx.x;             // 0..511
    if (c < HH) {
        const float* Wl = W1 + l * HH * HH + ED * HH;   // rows 64..127
        float u = 0.f, v = 0.f;
        for (int k = 0; k < ED; k++) {
            float w = Wl[k * HH + c];
            u = fmaf(edgeW[l * ED + k], w, u);
            v = fmaf(edgeb[l * ED + k], w, v);
        }
        g_UV[c] = u;
        g_UV[HH + c] = v;
    }
    for (int i = c; i < BB * 2 * HH; i += 512) g_STATS[i] = 0.f;
}

// ---------------- fused gather + GEMM1 + BN stats ---------------------------
// A-tile (64 rows x 64) built by CSR gather-sum of Hin[src]; then
// Z = A @ W1[:64,:] + s*u + deg*v + b1, plus per-channel sum/sumsq.
__global__ void __launch_bounds__(256) gemm1_kernel(const float* __restrict__ W1,
                                                    const float* __restrict__ b1,
                                                    int l, int insel) {
    extern __shared__ float sm[];
    float* sW   = sm;                 // 64*128
    float* sA   = sW + 64 * HH;       // 64*65
    float* sS   = sA + 64 * 65;       // 64
    float* sU   = sS + 64;            // 128
    float* sV   = sU + HH;            // 128
    float* sB   = sV + HH;            // 128
    float* sSum = sB + HH;            // 128
    float* sSq  = sSum + HH;          // 128
    int*   sOff = (int*)(sSq + HH);   // 65

    int tid = threadIdx.x;
    int b = blockIdx.y;
    int r0 = blockIdx.x * 64;

    const float4* Wg = (const float4*)(W1 + l * HH * HH);   // rows 0..63
    float4* sWv = (float4*)sW;
#pragma unroll
    for (int i = 0; i < 8; i++) sWv[tid + i * 256] = Wg[tid + i * 256];

    if (tid < HH) {
        sU[tid] = g_UV[tid];
        sV[tid] = g_UV[HH + tid];
        sB[tid] = b1[l * HH + tid];
        sSum[tid] = 0.f; sSq[tid] = 0.f;
    }
    if (tid < 64) {
        int r = r0 + tid;
        sS[tid] = (r < NN) ? g_S[b * NN + r] : 0.f;
    }
    if (tid < 65) {
        int r = r0 + tid;
        if (r > NN) r = NN;
        sOff[tid] = g_OFF[b * (NN + 1) + r];
    }
    __syncthreads();

    // ---- CSR gather: each warp handles 8 rows; lane owns cols lane, lane+32
    {
        const float* Hin = (insel ? g_H1 : g_H0) + b * NN * ED;
        const int* src = g_SRC + b * EE;
        int w = tid >> 5, lane = tid & 31;
#pragma unroll
        for (int j = 0; j < 8; j++) {
            int r = 8 * w + j;
            int gr = r0 + r;
            float a0 = 0.f, a1 = 0.f;
            if (gr < NN) {
                int e = sOff[r], end = sOff[r + 1];
                for (; e + 4 <= end; e += 4) {
                    int s0 = src[e], s1 = src[e + 1], s2 = src[e + 2], s3 = src[e + 3];
                    const float* p0 = Hin + s0 * ED;
                    const float* p1 = Hin + s1 * ED;
                    const float* p2 = Hin + s2 * ED;
                    const float* p3 = Hin + s3 * ED;
                    float x0 = p0[lane], y0 = p0[lane + 32];
                    float x1 = p1[lane], y1 = p1[lane + 32];
                    float x2 = p2[lane], y2 = p2[lane + 32];
                    float x3 = p3[lane], y3 = p3[lane + 32];
                    a0 += (x0 + x1) + (x2 + x3);
                    a1 += (y0 + y1) + (y2 + y3);
                }
                for (; e < end; e++) {
                    const float* p = Hin + src[e] * ED;
                    a0 += p[lane]; a1 += p[lane + 32];
                }
            }
            sA[r * 65 + lane] = a0;
            sA[r * 65 + lane + 32] = a1;
        }
    }
    __syncthreads();

    int tx = tid & 15, ty = tid >> 4;
    int c0 = tx * 4;
    float acc[4][8];
#pragma unroll
    for (int j = 0; j < 4; j++)
#pragma unroll
        for (int c = 0; c < 8; c++) acc[j][c] = 0.f;

#pragma unroll 8
    for (int k = 0; k < ED; k++) {
        float a[4];
#pragma unroll
        for (int j = 0; j < 4; j++) a[j] = sA[(4 * ty + j) * 65 + k];
        float4 w0 = *(const float4*)&sW[k * HH + c0];
        float4 w1 = *(const float4*)&sW[k * HH + 64 + c0];
#pragma unroll
        for (int j = 0; j < 4; j++) {
            acc[j][0] = fmaf(a[j], w0.x, acc[j][0]);
            acc[j][1] = fmaf(a[j], w0.y, acc[j][1]);
            acc[j][2] = fmaf(a[j], w0.z, acc[j][2]);
            acc[j][3] = fmaf(a[j], w0.w, acc[j][3]);
            acc[j][4] = fmaf(a[j], w1.x, acc[j][4]);
            acc[j][5] = fmaf(a[j], w1.y, acc[j][5]);
            acc[j][6] = fmaf(a[j], w1.z, acc[j][6]);
            acc[j][7] = fmaf(a[j], w1.w, acc[j][7]);
        }
    }

    float colsum[8], colsq[8];
#pragma unroll
    for (int c = 0; c < 8; c++) { colsum[c] = 0.f; colsq[c] = 0.f; }

#pragma unroll
    for (int j = 0; j < 4; j++) {
        int r = 4 * ty + j;
        int gr = r0 + r;
        if (gr < NN) {
            float s = sS[r];
            float d = (float)(sOff[r + 1] - sOff[r]);
            float z[8];
#pragma unroll
            for (int c = 0; c < 8; c++) {
                int col = (c < 4) ? (c0 + c) : (64 + c0 + c - 4);
                float zz = acc[j][c] + s * sU[col] + d * sV[col] + sB[col];
                z[c] = zz;
                colsum[c] += zz;
                colsq[c] += zz * zz;
            }
            *(float4*)(g_Z + (b * NN + gr) * HH + c0)      = make_float4(z[0], z[1], z[2], z[3]);
            *(float4*)(g_Z + (b * NN + gr) * HH + 64 + c0) = make_float4(z[4], z[5], z[6], z[7]);
        }
    }
#pragma unroll
    for (int c = 0; c < 8; c++) {
        int col = (c < 4) ? (c0 + c) : (64 + c0 + c - 4);
        atomicAdd(&sSum[col], colsum[c]);
        atomicAdd(&sSq[col], colsq[c]);
    }
    __syncthreads();
    if (tid < HH) {
        atomicAdd(&g_STATS[b * 2 * HH + tid], sSum[tid]);
        atomicAdd(&g_STATS[b * 2 * HH + HH + tid], sSq[tid]);
    }
}

// ---------------- BN finalize ------------------------------------------------
__global__ void bnfin_kernel(const float* __restrict__ gamma,
                             const float* __restrict__ beta, int l) {
    int i = threadIdx.x;             // 512 = B*128
    int b = i >> 7, c = i & 127;
    float sum = g_STATS[b * 2 * HH + c];
    float sq  = g_STATS[b * 2 * HH + HH + c];
    float m = sum * (1.0f / NN);
    float var = sq * (1.0f / NN) - m * m;
    float rs = rsqrtf(var + BN_EPS);
    float a = gamma[l * HH + c] * rs;
    g_AB[b * 2 * HH + c] = a;
    g_AB[b * 2 * HH + HH + c] = beta[l * HH + c] - m * a;
}

// ---------------- BN+ReLU+GEMM2 (+optional outer ReLU) ----------------------
__global__ void __launch_bounds__(256) gemm2_kernel(const float* __restrict__ W2,
                                                    const float* __restrict__ b2,
                                                    int l, int outsel,
                                                    float* __restrict__ dout,
                                                    int relu_out) {
    extern __shared__ float sm[];
    float* sW  = sm;                  // 128*64
    float* sT  = sW + HH * ED;        // 64*132
    float* sa  = sT + 64 * 132;       // 128
    float* sbb = sa + HH;             // 128
    float* sb2 = sbb + HH;            // 64

    int tid = threadIdx.x;
    int b = blockIdx.y;
    int r0 = blockIdx.x * 64;

    const float4* Wg = (const float4*)(W2 + l * HH * ED);
    float4* sWv = (float4*)sW;
#pragma unroll
    for (int i = 0; i < 8; i++) sWv[tid + i * 256] = Wg[tid + i * 256];
    if (tid < HH) { sa[tid] = g_AB[b * 2 * HH + tid]; sbb[tid] = g_AB[b * 2 * HH + HH + tid]; }
    if (tid < ED) sb2[tid] = b2[l * ED + tid];
    __syncthreads();

#pragma unroll
    for (int i = 0; i < 8; i++) {
        int idx4 = tid + i * 256;
        int r = idx4 >> 5, k4 = idx4 & 31;
        float4 v = make_float4(0.f, 0.f, 0.f, 0.f);
        if (r0 + r < NN) v = *(const float4*)(g_Z + (b * NN + r0 + r) * HH + k4 * 4);
        int k = k4 * 4;
        float t0 = fmaxf(fmaf(v.x, sa[k],     sbb[k]),     0.f);
        float t1 = fmaxf(fmaf(v.y, sa[k + 1], sbb[k + 1]), 0.f);
        float t2 = fmaxf(fmaf(v.z, sa[k + 2], sbb[k + 2]), 0.f);
        float t3 = fmaxf(fmaf(v.w, sa[k + 3], sbb[k + 3]), 0.f);
        *(float4*)&sT[r * 132 + k] = make_float4(t0, t1, t2, t3);
    }
    __syncthreads();

    int tx = tid & 15, ty = tid >> 4;
    int c0 = tx * 4;
    float acc[4][4];
#pragma unroll
    for (int j = 0; j < 4; j++)
#pragma unroll
        for (int c = 0; c < 4; c++) acc[j][c] = 0.f;

#pragma unroll 8
    for (int k = 0; k < HH; k++) {
        float4 w = *(const float4*)&sW[k * ED + c0];
#pragma unroll
        for (int j = 0; j < 4; j++) {
            float a = sT[(4 * ty + j) * 132 + k];
            acc[j][0] = fmaf(a, w.x, acc[j][0]);
            acc[j][1] = fmaf(a, w.y, acc[j][1]);
            acc[j][2] = fmaf(a, w.z, acc[j][2]);
            acc[j][3] = fmaf(a, w.w, acc[j][3]);
        }
    }

    float* outp = (outsel == 2) ? dout : (outsel ? g_H0 : g_H1);
#pragma unroll
    for (int j = 0; j < 4; j++) {
        int gr = r0 + 4 * ty + j;
        if (gr < NN) {
            float o0 = acc[j][0] + sb2[c0];
            float o1 = acc[j][1] + sb2[c0 + 1];
            float o2 = acc[j][2] + sb2[c0 + 2];
            float o3 = acc[j][3] + sb2[c0 + 3];
            if (relu_out) {
                o0 = fmaxf(o0, 0.f); o1 = fmaxf(o1, 0.f);
                o2 = fmaxf(o2, 0.f); o3 = fmaxf(o3, 0.f);
            }
            *(float4*)(outp + (b * NN + gr) * ED + c0) = make_float4(o0, o1, o2, o3);
        }
    }
}

// ---------------- launch ----------------------------------------------------
extern "C" void kernel_launch(void* const* d_in, const int* in_sizes, int n_in,
                              void* d_out, int out_size) {
    const float* x      = (const float*)d_in[0];
    const int*   ei     = (const int*)  d_in[1];
    const float* eattr  = (const float*)d_in[2];
    const float* inW    = (const float*)d_in[3];
    const float* inb    = (const float*)d_in[4];
    const float* edgeW  = (const float*)d_in[5];
    const float* edgeb  = (const float*)d_in[6];
    const float* W1     = (const float*)d_in[7];
    const float* b1     = (const float*)d_in[8];
    const float* gamma  = (const float*)d_in[9];
    const float* beta   = (const float*)d_in[10];
    const float* W2     = (const float*)d_in[11];
    const float* b2     = (const float*)d_in[12];
    float* out = (float*)d_out;

    const int G1_SMEM = (64 * HH + 64 * 65 + 64 + 5 * HH + 68) * 4;       // ~52.5KB
    const int G2_SMEM = (HH * ED + 64 * 132 + 2 * HH + ED) * 4;           // 67840
    cudaFuncSetAttribute(gemm1_kernel, cudaFuncAttributeMaxDynamicSharedMemorySize, G1_SMEM);
    cudaFuncSetAttribute(gemm2_kernel, cudaFuncAttributeMaxDynamicSharedMemorySize, G2_SMEM);

    detect_kernel<<<1, 256>>>(ei);
    zero_once_kernel<<<(BB * NN + 255) / 256, 256>>>();
    input_embed_kernel<<<BB * NN, 64>>>(x, inW, inb);
    count_kernel<<<(BB * EE + 255) / 256, 256>>>(ei, eattr);
    scan_kernel<<<BB, 1024>>>();
    fill_kernel<<<(BB * EE + 255) / 256, 256>>>(ei);

    dim3 ggrid((NN + 63) / 64, BB);
    for (int l = 0; l < NLAYER; l++) {
        int insel  = (l == 1) ? 1 : 0;                  // l0: H0, l1: H1, l2: H0
        int outsel = (l == 2) ? 2 : ((l == 0) ? 0 : 1); // l0->H1, l1->H0, l2->d_out
        uv_kernel<<<1, 512>>>(edgeW, edgeb, W1, l);
        gemm1_kernel<<<ggrid, 256, G1_SMEM>>>(W1, b1, l, insel);
        bnfin_kernel<<<1, BB * HH>>>(gamma, beta, l);
        gemm2_kernel<<<ggrid, 256, G2_SMEM>>>(W2, b2, l, outsel, out, (l < NLAYER - 1) ? 1 : 0);
    }
}

// round 10
// speedup vs baseline: 1.4312x; 1.1322x over previous
#include <cuda_runtime.h>
#include <cstdint>

// Problem constants
#define BB 4
#define NN 20000
#define EE 320000
#define ED 64
#define HH 128
#define INDIM 21
#define NLAYER 3
#define BN_EPS 1e-5f

// ---------------- scratch (device globals; no allocation allowed) ----------
__device__ float g_H0[BB*NN*ED];
__device__ float g_H1[BB*NN*ED];
__device__ float g_Z[BB*NN*HH];
__device__ float g_S[BB*NN];
__device__ float g_STATS[NLAYER*BB*2*HH];   // per-layer per-graph sum/sumsq
__device__ float g_UV[NLAYER*2*HH];         // per-layer u, v
__device__ float g_AB[BB*2*HH];
__device__ int   g_CNT[BB*NN];
__device__ int   g_OFF[BB*(NN+1)];
__device__ int   g_CUR[BB*NN];
__device__ int   g_SRC[BB*EE];
__device__ int   g_is64;

// ---------------- helpers ---------------------------------------------------
__device__ __forceinline__ uint32_t f2tf32(float f) {
    uint32_t r;
    asm("cvt.rna.tf32.f32 %0, %1;" : "=r"(r) : "f"(f));
    return r;
}
// split f into tf32 hi + tf32 lo (3xTF32 compensation)
__device__ __forceinline__ void tf32_split(float f, uint32_t& hi, uint32_t& lo) {
    hi = f2tf32(f);
    lo = f2tf32(f - __uint_as_float(hi));
}
__device__ __forceinline__ void mma_tf32(float* c, uint32_t a0, uint32_t a1,
                                         uint32_t a2, uint32_t a3,
                                         uint32_t bq0, uint32_t bq1) {
    asm volatile(
        "mma.sync.aligned.m16n8k8.row.col.f32.tf32.tf32.f32 "
        "{%0,%1,%2,%3}, {%4,%5,%6,%7}, {%8,%9}, {%0,%1,%2,%3};\n"
        : "+f"(c[0]), "+f"(c[1]), "+f"(c[2]), "+f"(c[3])
        : "r"(a0), "r"(a1), "r"(a2), "r"(a3), "r"(bq0), "r"(bq1));
}

// ---------------- dtype detection for edge_index ---------------------------
__global__ void detect_kernel(const int* __restrict__ ei) {
    int any = 0;
    for (int i = threadIdx.x; i < 4096; i += blockDim.x) {
        int p = 2 * (i * 312) + 1;
        if (ei[p] != 0) any = 1;
    }
    any = __syncthreads_or(any);
    if (threadIdx.x == 0) g_is64 = any ? 0 : 1;
}

// ---------------- zero launch-invariant scratch -----------------------------
__global__ void zero_once_kernel() {
    int tid = blockIdx.x * blockDim.x + threadIdx.x;
    if (tid < BB * NN) { g_CNT[tid] = 0; g_S[tid] = 0.f; }
    if (tid < NLAYER * BB * 2 * HH) g_STATS[tid] = 0.f;
}

// ---------------- CSR build: count ------------------------------------------
__global__ void count_kernel(const int* __restrict__ ei,
                             const float* __restrict__ eattr) {
    int gid = blockIdx.x * blockDim.x + threadIdx.x;
    if (gid >= BB * EE) return;
    int b = gid / EE, e = gid - b * EE;
    int base = b * 2 * EE;
    int dst = g_is64 ? ei[2 * (base + EE + e)] : ei[base + EE + e];
    atomicAdd(&g_CNT[b * NN + dst], 1);
    atomicAdd(&g_S[b * NN + dst], eattr[gid]);
}

// ---------------- CSR build: per-graph exclusive scan -----------------------
#define SCAN_CH 20
__global__ void __launch_bounds__(1024) scan_kernel() {
    int g = blockIdx.x;
    int tid = threadIdx.x;
    __shared__ int sdata[1024];
    int loc[SCAN_CH];
    int base = tid * SCAN_CH;
    int sum = 0;
#pragma unroll
    for (int i = 0; i < SCAN_CH; i++) {
        int idx = base + i;
        int v = (idx < NN) ? g_CNT[g * NN + idx] : 0;
        loc[i] = sum;
        sum += v;
    }
    sdata[tid] = sum;
    __syncthreads();
    for (int off = 1; off < 1024; off <<= 1) {
        int t = (tid >= off) ? sdata[tid - off] : 0;
        __syncthreads();
        sdata[tid] += t;
        __syncthreads();
    }
    int excl_base = sdata[tid] - sum;
#pragma unroll
    for (int i = 0; i < SCAN_CH; i++) {
        int idx = base + i;
        if (idx < NN) {
            int o = excl_base + loc[i];
            g_OFF[g * (NN + 1) + idx] = o;
            g_CUR[g * NN + idx] = o;
        }
    }
    if (tid == 1023) g_OFF[g * (NN + 1) + NN] = sdata[1023];
}

// ---------------- CSR build: fill -------------------------------------------
__global__ void fill_kernel(const int* __restrict__ ei) {
    int gid = blockIdx.x * blockDim.x + threadIdx.x;
    if (gid >= BB * EE) return;
    int b = gid / EE, e = gid - b * EE;
    int base = b * 2 * EE;
    int src, dst;
    if (g_is64) { src = ei[2 * (base + e)]; dst = ei[2 * (base + EE + e)]; }
    else        { src = ei[base + e];       dst = ei[base + EE + e];       }
    int pos = atomicAdd(&g_CUR[b * NN + dst], 1);
    g_SRC[b * EE + pos] = src;
}

// ---------------- layer-0 input embedding (4 rows / block) -----------------
__global__ void __launch_bounds__(256) input_embed_kernel(
        const float* __restrict__ x, const float* __restrict__ inW,
        const float* __restrict__ inb) {
    __shared__ float sx[4][INDIM];
    int r4 = blockIdx.x * 4;
    int lr = threadIdx.x >> 6, c = threadIdx.x & 63;
    if (threadIdx.x < 4 * INDIM) {
        int rr = threadIdx.x / INDIM, cc = threadIdx.x - rr * INDIM;
        sx[rr][cc] = x[(r4 + rr) * INDIM + cc];
    }
    __syncthreads();
    float acc = inb[c];
#pragma unroll
    for (int k = 0; k < INDIM; k++) acc = fmaf(sx[lr][k], inW[k * ED + c], acc);
    g_H0[(r4 + lr) * ED + c] = acc;
}

// ---------------- u/v precompute for ALL layers -----------------------------
__global__ void uv_all_kernel(const float* __restrict__ edgeW,
                              const float* __restrict__ edgeb,
                              const float* __restrict__ W1) {
    int l = blockIdx.x;
    int c = threadIdx.x;             // 0..127
    const float* Wl = W1 + l * HH * HH + ED * HH;   // rows 64..127
    float u = 0.f, v = 0.f;
#pragma unroll 8
    for (int k = 0; k < ED; k++) {
        float w = Wl[k * HH + c];
        u = fmaf(edgeW[l * ED + k], w, u);
        v = fmaf(edgeb[l * ED + k], w, v);
    }
    g_UV[l * 2 * HH + c] = u;
    g_UV[l * 2 * HH + HH + c] = v;
}

// ---------------- fused gather + 3xTF32 MMA GEMM1 + BN stats ----------------
// Block: 64 rows x 128 cols, 256 threads (8 warps: warp = 16 rows x 64 cols).
__global__ void __launch_bounds__(256) gemm1_kernel(const float* __restrict__ W1,
                                                    const float* __restrict__ b1,
                                                    int l, int insel) {
    extern __shared__ float sm[];
    float* sW   = sm;                 // 64*136 fp32
    float* sA   = sW + 64 * 136;      // 64*68  fp32
    float* sS   = sA + 64 * 68;       // 64
    float* sU   = sS + 64;            // 128
    float* sV   = sU + HH;            // 128
    float* sB   = sV + HH;            // 128
    float* sSum = sB + HH;            // 128
    float* sSq  = sSum + HH;          // 128
    int*   sOff = (int*)(sSq + HH);   // 65

    int tid = threadIdx.x;
    int b = blockIdx.y;
    int r0 = blockIdx.x * 64;

    // W1[l] rows 0..63 -> fp32 smem (pad 136)
    {
        const float4* Wg = (const float4*)(W1 + l * HH * HH);
#pragma unroll
        for (int i = 0; i < 8; i++) {
            int idx = tid + i * 256;          // 2048 float4
            float4 v = Wg[idx];
            int k = idx >> 5, n4 = idx & 31;
            *(float4*)&sW[k * 136 + n4 * 4] = v;
        }
    }
    if (tid < HH) {
        sU[tid] = g_UV[l * 2 * HH + tid];
        sV[tid] = g_UV[l * 2 * HH + HH + tid];
        sB[tid] = b1[l * HH + tid];
        sSum[tid] = 0.f; sSq[tid] = 0.f;
    }
    if (tid < 64) {
        int r = r0 + tid;
        sS[tid] = (r < NN) ? g_S[b * NN + r] : 0.f;
    }
    if (tid < 65) {
        int r = r0 + tid;
        if (r > NN) r = NN;
        sOff[tid] = g_OFF[b * (NN + 1) + r];
    }
    __syncthreads();

    // CSR gather -> sA (fp32, pad 68). Warp w handles rows 8w..8w+7.
    {
        const float* Hin = (insel ? g_H1 : g_H0) + b * NN * ED;
        const int* src = g_SRC + b * EE;
        int w = tid >> 5, lane = tid & 31;
#pragma unroll
        for (int j = 0; j < 8; j++) {
            int r = 8 * w + j;
            int gr = r0 + r;
            float a0 = 0.f, a1 = 0.f;
            if (gr < NN) {
                int e = sOff[r], end = sOff[r + 1];
                for (; e + 4 <= end; e += 4) {
                    int s0 = src[e], s1 = src[e + 1], s2 = src[e + 2], s3 = src[e + 3];
                    const float* p0 = Hin + s0 * ED;
                    const float* p1 = Hin + s1 * ED;
                    const float* p2 = Hin + s2 * ED;
                    const float* p3 = Hin + s3 * ED;
                    float x0 = p0[lane], y0 = p0[lane + 32];
                    float x1 = p1[lane], y1 = p1[lane + 32];
                    float x2 = p2[lane], y2 = p2[lane + 32];
                    float x3 = p3[lane], y3 = p3[lane + 32];
                    a0 += (x0 + x1) + (x2 + x3);
                    a1 += (y0 + y1) + (y2 + y3);
                }
                for (; e < end; e++) {
                    const float* p = Hin + src[e] * ED;
                    a0 += p[lane]; a1 += p[lane + 32];
                }
            }
            sA[r * 68 + lane]      = a0;
            sA[r * 68 + lane + 32] = a1;
        }
    }
    __syncthreads();

    // MMA mainloop (3xTF32: hi*hi + lo*hi + hi*lo)
    int w = tid >> 5, lane = tid & 31;
    int gid = lane >> 2, tig = lane & 3;
    int wm = w & 3, wn = w >> 2;
    int m0 = wm * 16, nb = wn * 64;

    float acc[8][4];
#pragma unroll
    for (int nt = 0; nt < 8; nt++)
#pragma unroll
        for (int c = 0; c < 4; c++) acc[nt][c] = 0.f;

#pragma unroll
    for (int ks = 0; ks < 8; ks++) {
        int k0 = ks * 8;
        float af0 = sA[(m0 + gid) * 68 + k0 + tig];
        float af1 = sA[(m0 + gid + 8) * 68 + k0 + tig];
        float af2 = sA[(m0 + gid) * 68 + k0 + tig + 4];
        float af3 = sA[(m0 + gid + 8) * 68 + k0 + tig + 4];
        uint32_t ah0, al0, ah1, al1, ah2, al2, ah3, al3;
        tf32_split(af0, ah0, al0);
        tf32_split(af1, ah1, al1);
        tf32_split(af2, ah2, al2);
        tf32_split(af3, ah3, al3);
#pragma unroll
        for (int nt = 0; nt < 8; nt++) {
            int n = nb + nt * 8;
            float bf0 = sW[(k0 + tig) * 136 + n + gid];
            float bf1 = sW[(k0 + tig + 4) * 136 + n + gid];
            uint32_t bh0, bl0, bh1, bl1;
            tf32_split(bf0, bh0, bl0);
            tf32_split(bf1, bh1, bl1);
            mma_tf32(acc[nt], ah0, ah1, ah2, ah3, bh0, bh1);
            mma_tf32(acc[nt], al0, al1, al2, al3, bh0, bh1);
            mma_tf32(acc[nt], ah0, ah1, ah2, ah3, bl0, bl1);
        }
    }

    // Epilogue: add rank-1 edge terms + bias, write Z, reduce BN stats
    int lr0 = m0 + gid, lr1 = lr0 + 8;
    int gr0 = r0 + lr0, gr1 = r0 + lr1;
    bool v0 = gr0 < NN, v1 = gr1 < NN;
    float s0 = sS[lr0], d0 = (float)(sOff[lr0 + 1] - sOff[lr0]);
    float s1 = sS[lr1], d1 = (float)(sOff[lr1 + 1] - sOff[lr1]);
    float* Zb = g_Z + (size_t)b * NN * HH;

#pragma unroll
    for (int nt = 0; nt < 8; nt++) {
        int c0 = nb + nt * 8 + tig * 2, c1 = c0 + 1;
        float u0 = sU[c0], u1 = sU[c1];
        float w0 = sV[c0], w1 = sV[c1];
        float e0 = sB[c0], e1 = sB[c1];
        float z00 = acc[nt][0] + s0 * u0 + d0 * w0 + e0;
        float z01 = acc[nt][1] + s0 * u1 + d0 * w1 + e1;
        float z10 = acc[nt][2] + s1 * u0 + d1 * w0 + e0;
        float z11 = acc[nt][3] + s1 * u1 + d1 * w1 + e1;
        if (v0) *(float2*)&Zb[(size_t)gr0 * HH + c0] = make_float2(z00, z01);
        if (v1) *(float2*)&Zb[(size_t)gr1 * HH + c0] = make_float2(z10, z11);
        float t00 = v0 ? z00 : 0.f, t01 = v0 ? z01 : 0.f;
        float t10 = v1 ? z10 : 0.f, t11 = v1 ? z11 : 0.f;
        float sum0 = t00 + t10, sum1 = t01 + t11;
        float sq0 = t00 * t00 + t10 * t10, sq1 = t01 * t01 + t11 * t11;
#pragma unroll
        for (int o = 4; o < 32; o <<= 1) {
            sum0 += __shfl_xor_sync(0xffffffffu, sum0, o);
            sum1 += __shfl_xor_sync(0xffffffffu, sum1, o);
            sq0  += __shfl_xor_sync(0xffffffffu, sq0, o);
            sq1  += __shfl_xor_sync(0xffffffffu, sq1, o);
        }
        if (gid == 0) {
            atomicAdd(&sSum[c0], sum0); atomicAdd(&sSum[c1], sum1);
            atomicAdd(&sSq[c0], sq0);   atomicAdd(&sSq[c1], sq1);
        }
    }
    __syncthreads();
    if (tid < HH) {
        float* st = g_STATS + (size_t)(l * BB + b) * 2 * HH;
        atomicAdd(&st[tid], sSum[tid]);
        atomicAdd(&st[HH + tid], sSq[tid]);
    }
}

// ---------------- BN finalize ------------------------------------------------
__global__ void bnfin_kernel(const float* __restrict__ gamma,
                             const float* __restrict__ beta, int l) {
    int i = threadIdx.x;             // 512 = B*128
    int b = i >> 7, c = i & 127;
    const float* st = g_STATS + (size_t)(l * BB + b) * 2 * HH;
    float sum = st[c];
    float sq  = st[HH + c];
    float m = sum * (1.0f / NN);
    float var = sq * (1.0f / NN) - m * m;
    float rs = rsqrtf(var + BN_EPS);
    float a = gamma[l * HH + c] * rs;
    g_AB[b * 2 * HH + c] = a;
    g_AB[b * 2 * HH + HH + c] = beta[l * HH + c] - m * a;
}

// ---------------- BN+ReLU + 3xTF32 MMA GEMM2 (+optional outer ReLU) ---------
// Block: 64 rows x 64 cols, 256 threads (8 warps: warp = 16 rows x 32 cols).
__global__ void __launch_bounds__(256) gemm2_kernel(const float* __restrict__ W2,
                                                    const float* __restrict__ b2,
                                                    int l, int outsel,
                                                    float* __restrict__ dout,
                                                    int relu_out) {
    extern __shared__ float sm[];
    float* sW  = sm;                  // 128*72 fp32
    float* sT  = sW + HH * 72;        // 64*132 fp32
    float* sa  = sT + 64 * 132;       // 128
    float* sbb = sa + HH;             // 128
    float* sb2 = sbb + HH;            // 64

    int tid = threadIdx.x;
    int b = blockIdx.y;
    int r0 = blockIdx.x * 64;

    {
        const float4* Wg = (const float4*)(W2 + l * HH * ED);
#pragma unroll
        for (int i = 0; i < 8; i++) {
            int idx = tid + i * 256;          // 2048 float4
            float4 v = Wg[idx];
            int k = idx >> 4, n4 = idx & 15;
            *(float4*)&sW[k * 72 + n4 * 4] = v;
        }
    }
    if (tid < HH) { sa[tid] = g_AB[b * 2 * HH + tid]; sbb[tid] = g_AB[b * 2 * HH + HH + tid]; }
    if (tid < ED) sb2[tid] = b2[l * ED + tid];
    __syncthreads();

    // Z tile -> BN + ReLU -> fp32 smem (pad 132)
    const float* Zb = g_Z + (size_t)b * NN * HH;
#pragma unroll
    for (int i = 0; i < 8; i++) {
        int idx4 = tid + i * 256;             // 2048 float4
        int r = idx4 >> 5, k4 = idx4 & 31;
        float4 v = make_float4(0.f, 0.f, 0.f, 0.f);
        if (r0 + r < NN) v = *(const float4*)&Zb[(size_t)(r0 + r) * HH + k4 * 4];
        int k = k4 * 4;
        float4 t;
        t.x = fmaxf(fmaf(v.x, sa[k],     sbb[k]),     0.f);
        t.y = fmaxf(fmaf(v.y, sa[k + 1], sbb[k + 1]), 0.f);
        t.z = fmaxf(fmaf(v.z, sa[k + 2], sbb[k + 2]), 0.f);
        t.w = fmaxf(fmaf(v.w, sa[k + 3], sbb[k + 3]), 0.f);
        *(float4*)&sT[r * 132 + k] = t;
    }
    __syncthreads();

    int w = tid >> 5, lane = tid & 31;
    int gid = lane >> 2, tig = lane & 3;
    int wm = w & 3, wn = w >> 2;
    int m0 = wm * 16, nb = wn * 32;

    float acc[4][4];
#pragma unroll
    for (int nt = 0; nt < 4; nt++)
#pragma unroll
        for (int c = 0; c < 4; c++) acc[nt][c] = 0.f;

#pragma unroll
    for (int ks = 0; ks < 16; ks++) {
        int k0 = ks * 8;
        float af0 = sT[(m0 + gid) * 132 + k0 + tig];
        float af1 = sT[(m0 + gid + 8) * 132 + k0 + tig];
        float af2 = sT[(m0 + gid) * 132 + k0 + tig + 4];
        float af3 = sT[(m0 + gid + 8) * 132 + k0 + tig + 4];
        uint32_t ah0, al0, ah1, al1, ah2, al2, ah3, al3;
        tf32_split(af0, ah0, al0);
        tf32_split(af1, ah1, al1);
        tf32_split(af2, ah2, al2);
        tf32_split(af3, ah3, al3);
#pragma unroll
        for (int nt = 0; nt < 4; nt++) {
            int n = nb + nt * 8;
            float bf0 = sW[(k0 + tig) * 72 + n + gid];
            float bf1 = sW[(k0 + tig + 4) * 72 + n + gid];
            uint32_t bh0, bl0, bh1, bl1;
            tf32_split(bf0, bh0, bl0);
            tf32_split(bf1, bh1, bl1);
            mma_tf32(acc[nt], ah0, ah1, ah2, ah3, bh0, bh1);
            mma_tf32(acc[nt], al0, al1, al2, al3, bh0, bh1);
            mma_tf32(acc[nt], ah0, ah1, ah2, ah3, bl0, bl1);
        }
    }

    float* outp = (outsel == 2) ? dout : (outsel ? g_H0 : g_H1);
    int gr0 = r0 + m0 + gid, gr1 = gr0 + 8;
#pragma unroll
    for (int nt = 0; nt < 4; nt++) {
        int c0 = nb + nt * 8 + tig * 2, c1 = c0 + 1;
        float o00 = acc[nt][0] + sb2[c0];
        float o01 = acc[nt][1] + sb2[c1];
        float o10 = acc[nt][2] + sb2[c0];
        float o11 = acc[nt][3] + sb2[c1];
        if (relu_out) {
            o00 = fmaxf(o00, 0.f); o01 = fmaxf(o01, 0.f);
            o10 = fmaxf(o10, 0.f); o11 = fmaxf(o11, 0.f);
        }
        if (gr0 < NN) *(float2*)&outp[(size_t)(b * NN + gr0) * ED + c0] = make_float2(o00, o01);
        if (gr1 < NN) *(float2*)&outp[(size_t)(b * NN + gr1) * ED + c0] = make_float2(o10, o11);
    }
}

// ---------------- launch ----------------------------------------------------
extern "C" void kernel_launch(void* const* d_in, const int* in_sizes, int n_in,
                              void* d_out, int out_size) {
    const float* x      = (const float*)d_in[0];
    const int*   ei     = (const int*)  d_in[1];
    const float* eattr  = (const float*)d_in[2];
    const float* inW    = (const float*)d_in[3];
    const float* inb    = (const float*)d_in[4];
    const float* edgeW  = (const float*)d_in[5];
    const float* edgeb  = (const float*)d_in[6];
    const float* W1     = (const float*)d_in[7];
    const float* b1     = (const float*)d_in[8];
    const float* gamma  = (const float*)d_in[9];
    const float* beta   = (const float*)d_in[10];
    const float* W2     = (const float*)d_in[11];
    const float* b2     = (const float*)d_in[12];
    float* out = (float*)d_out;

    const int G1_SMEM = (64 * 136 + 64 * 68 + 64 + 5 * HH + 68) * 4;   // ~55.6KB
    const int G2_SMEM = (HH * 72 + 64 * 132 + 2 * HH + ED) * 4;        // ~73.2KB
    cudaFuncSetAttribute(gemm1_kernel, cudaFuncAttributeMaxDynamicSharedMemorySize, G1_SMEM);
    cudaFuncSetAttribute(gemm2_kernel, cudaFuncAttributeMaxDynamicSharedMemorySize, G2_SMEM);

    detect_kernel<<<1, 256>>>(ei);
    zero_once_kernel<<<(BB * NN + 255) / 256, 256>>>();
    input_embed_kernel<<<BB * NN / 4, 256>>>(x, inW, inb);
    uv_all_kernel<<<NLAYER, HH>>>(edgeW, edgeb, W1);
    count_kernel<<<(BB * EE + 255) / 256, 256>>>(ei, eattr);
    scan_kernel<<<BB, 1024>>>();
    fill_kernel<<<(BB * EE + 255) / 256, 256>>>(ei);

    dim3 ggrid((NN + 63) / 64, BB);
    for (int l = 0; l < NLAYER; l++) {
        int insel  = (l == 1) ? 1 : 0;                  // l0: H0, l1: H1, l2: H0
        int outsel = (l == 2) ? 2 : ((l == 0) ? 0 : 1); // l0->H1, l1->H0, l2->d_out
        gemm1_kernel<<<ggrid, 256, G1_SMEM>>>(W1, b1, l, insel);
        bnfin_kernel<<<1, BB * HH>>>(gamma, beta, l);
        gemm2_kernel<<<ggrid, 256, G2_SMEM>>>(W2, b2, l, outsel, out, (l < NLAYER - 1) ? 1 : 0);
    }
}